// round 12
// baseline (speedup 1.0000x reference)
#include <cuda_runtime.h>
#include <math.h>

#define NT   2048      // tokens (2*1024)
#define NH   2048      // hidden
#define NE   64        // experts
#define NK   6         // top_k
#define NF   768       // moe intermediate
#define NG   8         // groups
#define EPG  8         // experts per group
#define NKG  4         // topk groups
#define NCAP 384       // capacity per expert
#define RSCALE 2.5f

// ---------------- scratch (device globals; no allocation allowed) ----------
__device__ float g_logits[NT * NE];
__device__ int   g_cnt[NE];
__device__ int   g_tok[NE * NCAP];
__device__ float g_wgt[NE * NCAP];
__device__ float g_hbuf[(size_t)NE * NCAP * NF];   // 75.5 MB
__device__ float g_sbuf[(size_t)NT * NF];          // 6.3 MB

// ---------------------------------------------------------------------------
__global__ void zero_cnt_kernel() {
    int i = threadIdx.x;
    if (i < NE) g_cnt[i] = 0;
}

// ---------------- router logits: X[NT,NH] @ gate_w[NH,NE] -> g_logits ------
__global__ void router_gemm(const float* __restrict__ X,
                            const float* __restrict__ Wg) {
    __shared__ __align__(16) float As[64][16];
    __shared__ __align__(16) float Bs[16][64];
    int bm = blockIdx.x * 64;
    int tid = threadIdx.x;
    int tx = tid & 15, ty = tid >> 4;
    int arow = tid >> 2, akg = tid & 3;
    int brow = tid >> 4, bng = tid & 15;
    float acc[4][4] = {};
    for (int k0 = 0; k0 < NH; k0 += 16) {
        *(float4*)&As[arow][akg * 4] =
            *(const float4*)&X[(size_t)(bm + arow) * NH + k0 + akg * 4];
        *(float4*)&Bs[brow][bng * 4] =
            *(const float4*)&Wg[(size_t)(k0 + brow) * NE + bng * 4];
        __syncthreads();
#pragma unroll
        for (int kk = 0; kk < 16; kk++) {
            float4 b4 = *(const float4*)&Bs[kk][tx * 4];
            float a[4];
#pragma unroll
            for (int i = 0; i < 4; i++) a[i] = As[ty * 4 + i][kk];
#pragma unroll
            for (int i = 0; i < 4; i++) {
                acc[i][0] += a[i] * b4.x;
                acc[i][1] += a[i] * b4.y;
                acc[i][2] += a[i] * b4.z;
                acc[i][3] += a[i] * b4.w;
            }
        }
        __syncthreads();
    }
#pragma unroll
    for (int i = 0; i < 4; i++)
#pragma unroll
        for (int j = 0; j < 4; j++)
            g_logits[(size_t)(bm + ty * 4 + i) * NE + tx * 4 + j] = acc[i][j];
}

// ---------------- grouped top-k routing + scatter ---------------------------
__global__ void topk_route(const float* __restrict__ bias) {
    int t = blockIdx.x * blockDim.x + threadIdx.x;
    if (t >= NT) return;
    float s[NE], sb[NE];
#pragma unroll 8
    for (int e = 0; e < NE; e++) {
        float l = g_logits[(size_t)t * NE + e];
        float sv = 1.f / (1.f + expf(-l));
        s[e] = sv;
        sb[e] = sv + bias[e];
    }
    // group scores = sum of top-2 biased scores per group
    float gsc[NG];
#pragma unroll
    for (int g = 0; g < NG; g++) {
        float m1 = -INFINITY, m2 = -INFINITY;
#pragma unroll
        for (int j = 0; j < EPG; j++) {
            float v = sb[g * EPG + j];
            if (v > m1) { m2 = m1; m1 = v; }
            else if (v > m2) { m2 = v; }
        }
        gsc[g] = m1 + m2;
    }
    // top-NKG groups (ties -> lowest index, matching jax top_k)
    bool gsel[NG];
#pragma unroll
    for (int g = 0; g < NG; g++) gsel[g] = false;
    for (int r = 0; r < NKG; r++) {
        int bi = 0; float bv = -INFINITY;
        for (int g = 0; g < NG; g++)
            if (!gsel[g] && gsc[g] > bv) { bv = gsc[g]; bi = g; }
        gsel[bi] = true;
    }
    // top-NK experts within selected groups by biased score
    bool used[NE];
#pragma unroll
    for (int e = 0; e < NE; e++) used[e] = false;
    int ids[NK];
    float ws[NK];
    float wsum = 0.f;
    for (int r = 0; r < NK; r++) {
        int bi = 0; float bv = -INFINITY;
        for (int e = 0; e < NE; e++) {
            if (used[e] || !gsel[e / EPG]) continue;
            if (sb[e] > bv) { bv = sb[e]; bi = e; }
        }
        used[bi] = true;
        ids[r] = bi;
        ws[r] = s[bi];   // weights come from UNBIASED scores
        wsum += s[bi];
    }
    float inv = RSCALE / wsum;
    for (int r = 0; r < NK; r++) {
        int e = ids[r];
        int slot = atomicAdd(&g_cnt[e], 1);
        if (slot < NCAP) {
            g_tok[e * NCAP + slot] = t;
            g_wgt[e * NCAP + slot] = ws[r] * inv;
        }
    }
}

// ---------------- grouped SwiGLU GEMM1: hbuf = silu(Xe@Wg) * (Xe@Wu) --------
__global__ void moe_gemm1(const float* __restrict__ X,
                          const float* __restrict__ Wg,
                          const float* __restrict__ Wu) {
    int e = blockIdx.z;
    int cnt = g_cnt[e]; if (cnt > NCAP) cnt = NCAP;
    int row0 = blockIdx.y * 64;
    if (row0 >= cnt) return;
    int n0 = blockIdx.x * 64;

    __shared__ __align__(16) float As[64][16];
    __shared__ __align__(16) float Bg[16][64];
    __shared__ __align__(16) float Bu[16][64];
    __shared__ int toks[64];

    int tid = threadIdx.x;
    if (tid < 64) {
        int r = row0 + tid;
        toks[tid] = (r < cnt) ? g_tok[e * NCAP + r] : 0;
    }
    __syncthreads();

    int tx = tid & 15, ty = tid >> 4;
    int arow = tid >> 2, akg = tid & 3;
    int brow = tid >> 4, bng = tid & 15;
    const float* wg = Wg + (size_t)e * NH * NF;
    const float* wu = Wu + (size_t)e * NH * NF;
    float ag[4][4] = {}, au[4][4] = {};

    for (int k0 = 0; k0 < NH; k0 += 16) {
        *(float4*)&As[arow][akg * 4] =
            *(const float4*)&X[(size_t)toks[arow] * NH + k0 + akg * 4];
        *(float4*)&Bg[brow][bng * 4] =
            *(const float4*)&wg[(size_t)(k0 + brow) * NF + n0 + bng * 4];
        *(float4*)&Bu[brow][bng * 4] =
            *(const float4*)&wu[(size_t)(k0 + brow) * NF + n0 + bng * 4];
        __syncthreads();
#pragma unroll
        for (int kk = 0; kk < 16; kk++) {
            float4 bg4 = *(const float4*)&Bg[kk][tx * 4];
            float4 bu4 = *(const float4*)&Bu[kk][tx * 4];
            float a[4];
#pragma unroll
            for (int i = 0; i < 4; i++) a[i] = As[ty * 4 + i][kk];
#pragma unroll
            for (int i = 0; i < 4; i++) {
                ag[i][0] += a[i] * bg4.x; ag[i][1] += a[i] * bg4.y;
                ag[i][2] += a[i] * bg4.z; ag[i][3] += a[i] * bg4.w;
                au[i][0] += a[i] * bu4.x; au[i][1] += a[i] * bu4.y;
                au[i][2] += a[i] * bu4.z; au[i][3] += a[i] * bu4.w;
            }
        }
        __syncthreads();
    }

    float* hb = g_hbuf + (size_t)e * NCAP * NF;
#pragma unroll
    for (int i = 0; i < 4; i++) {
        int r = row0 + ty * 4 + i;
        if (r >= cnt) continue;
#pragma unroll
        for (int j = 0; j < 4; j++) {
            float g = ag[i][j];
            float h = (g / (1.f + expf(-g))) * au[i][j];
            hb[(size_t)r * NF + n0 + tx * 4 + j] = h;
        }
    }
}

// ---------------- grouped down GEMM: out += w * (hbuf @ Wd) -----------------
__global__ void moe_gemm2(const float* __restrict__ Wd,
                          float* __restrict__ out) {
    int e = blockIdx.z;
    int cnt = g_cnt[e]; if (cnt > NCAP) cnt = NCAP;
    int row0 = blockIdx.y * 64;
    if (row0 >= cnt) return;
    int n0 = blockIdx.x * 64;

    __shared__ __align__(16) float As[64][16];
    __shared__ __align__(16) float Bs[16][64];

    const float* hb = g_hbuf + (size_t)e * NCAP * NF;
    const float* wd = Wd + (size_t)e * NF * NH;

    int tid = threadIdx.x;
    int tx = tid & 15, ty = tid >> 4;
    int arow = tid >> 2, akg = tid & 3;
    int brow = tid >> 4, bng = tid & 15;
    float acc[4][4] = {};

    for (int k0 = 0; k0 < NF; k0 += 16) {
        *(float4*)&As[arow][akg * 4] =
            *(const float4*)&hb[(size_t)(row0 + arow) * NF + k0 + akg * 4];
        *(float4*)&Bs[brow][bng * 4] =
            *(const float4*)&wd[(size_t)(k0 + brow) * NH + n0 + bng * 4];
        __syncthreads();
#pragma unroll
        for (int kk = 0; kk < 16; kk++) {
            float4 b4 = *(const float4*)&Bs[kk][tx * 4];
            float a[4];
#pragma unroll
            for (int i = 0; i < 4; i++) a[i] = As[ty * 4 + i][kk];
#pragma unroll
            for (int i = 0; i < 4; i++) {
                acc[i][0] += a[i] * b4.x; acc[i][1] += a[i] * b4.y;
                acc[i][2] += a[i] * b4.z; acc[i][3] += a[i] * b4.w;
            }
        }
        __syncthreads();
    }

#pragma unroll
    for (int i = 0; i < 4; i++) {
        int r = row0 + ty * 4 + i;
        if (r >= cnt) continue;
        int tok = g_tok[e * NCAP + r];
        float w = g_wgt[e * NCAP + r];
        float* op = out + (size_t)tok * NH + n0 + tx * 4;
#pragma unroll
        for (int j = 0; j < 4; j++)
            atomicAdd(op + j, acc[i][j] * w);
    }
}

// ---------------- shared expert GEMM1: sbuf = silu(X@Wg)*(X@Wu) -------------
__global__ void shared_gemm1(const float* __restrict__ X,
                             const float* __restrict__ Wg,
                             const float* __restrict__ Wu) {
    int row0 = blockIdx.y * 64;
    int n0 = blockIdx.x * 64;

    __shared__ __align__(16) float As[64][16];
    __shared__ __align__(16) float Bg[16][64];
    __shared__ __align__(16) float Bu[16][64];

    int tid = threadIdx.x;
    int tx = tid & 15, ty = tid >> 4;
    int arow = tid >> 2, akg = tid & 3;
    int brow = tid >> 4, bng = tid & 15;
    float ag[4][4] = {}, au[4][4] = {};

    for (int k0 = 0; k0 < NH; k0 += 16) {
        *(float4*)&As[arow][akg * 4] =
            *(const float4*)&X[(size_t)(row0 + arow) * NH + k0 + akg * 4];
        *(float4*)&Bg[brow][bng * 4] =
            *(const float4*)&Wg[(size_t)(k0 + brow) * NF + n0 + bng * 4];
        *(float4*)&Bu[brow][bng * 4] =
            *(const float4*)&Wu[(size_t)(k0 + brow) * NF + n0 + bng * 4];
        __syncthreads();
#pragma unroll
        for (int kk = 0; kk < 16; kk++) {
            float4 bg4 = *(const float4*)&Bg[kk][tx * 4];
            float4 bu4 = *(const float4*)&Bu[kk][tx * 4];
            float a[4];
#pragma unroll
            for (int i = 0; i < 4; i++) a[i] = As[ty * 4 + i][kk];
#pragma unroll
            for (int i = 0; i < 4; i++) {
                ag[i][0] += a[i] * bg4.x; ag[i][1] += a[i] * bg4.y;
                ag[i][2] += a[i] * bg4.z; ag[i][3] += a[i] * bg4.w;
                au[i][0] += a[i] * bu4.x; au[i][1] += a[i] * bu4.y;
                au[i][2] += a[i] * bu4.z; au[i][3] += a[i] * bu4.w;
            }
        }
        __syncthreads();
    }

#pragma unroll
    for (int i = 0; i < 4; i++) {
        int r = row0 + ty * 4 + i;
#pragma unroll
        for (int j = 0; j < 4; j++) {
            float g = ag[i][j];
            float h = (g / (1.f + expf(-g))) * au[i][j];
            g_sbuf[(size_t)r * NF + n0 + tx * 4 + j] = h;
        }
    }
}

// ---------------- shared expert GEMM2: out = sbuf @ Wd (plain store) --------
__global__ void shared_gemm2(const float* __restrict__ Wd,
                             float* __restrict__ out) {
    int row0 = blockIdx.y * 64;
    int n0 = blockIdx.x * 64;

    __shared__ __align__(16) float As[64][16];
    __shared__ __align__(16) float Bs[16][64];

    int tid = threadIdx.x;
    int tx = tid & 15, ty = tid >> 4;
    int arow = tid >> 2, akg = tid & 3;
    int brow = tid >> 4, bng = tid & 15;
    float acc[4][4] = {};

    for (int k0 = 0; k0 < NF; k0 += 16) {
        *(float4*)&As[arow][akg * 4] =
            *(const float4*)&g_sbuf[(size_t)(row0 + arow) * NF + k0 + akg * 4];
        *(float4*)&Bs[brow][bng * 4] =
            *(const float4*)&Wd[(size_t)(k0 + brow) * NH + n0 + bng * 4];
        __syncthreads();
#pragma unroll
        for (int kk = 0; kk < 16; kk++) {
            float4 b4 = *(const float4*)&Bs[kk][tx * 4];
            float a[4];
#pragma unroll
            for (int i = 0; i < 4; i++) a[i] = As[ty * 4 + i][kk];
#pragma unroll
            for (int i = 0; i < 4; i++) {
                acc[i][0] += a[i] * b4.x; acc[i][1] += a[i] * b4.y;
                acc[i][2] += a[i] * b4.z; acc[i][3] += a[i] * b4.w;
            }
        }
        __syncthreads();
    }

#pragma unroll
    for (int i = 0; i < 4; i++) {
        int r = row0 + ty * 4 + i;
#pragma unroll
        for (int j = 0; j < 4; j++)
            out[(size_t)r * NH + n0 + tx * 4 + j] = acc[i][j];
    }
}

// ---------------------------------------------------------------------------
extern "C" void kernel_launch(void* const* d_in, const int* in_sizes, int n_in,
                              void* d_out, int out_size) {
    const float* x       = (const float*)d_in[0];
    const float* gate_w  = (const float*)d_in[1];
    const float* bias    = (const float*)d_in[2];
    const float* w_gate  = (const float*)d_in[3];
    const float* w_up    = (const float*)d_in[4];
    const float* w_down  = (const float*)d_in[5];
    const float* ws_gate = (const float*)d_in[6];
    const float* ws_up   = (const float*)d_in[7];
    const float* ws_down = (const float*)d_in[8];
    float* out = (float*)d_out;

    zero_cnt_kernel<<<1, 64>>>();
    router_gemm<<<NT / 64, 256>>>(x, gate_w);
    topk_route<<<NT / 256, 256>>>(bias);

    // shared expert first: plain stores initialize the (poisoned) output
    shared_gemm1<<<dim3(NF / 64, NT / 64), 256>>>(x, ws_gate, ws_up);
    shared_gemm2<<<dim3(NH / 64, NT / 64), 256>>>(ws_down, out);

    // routed experts: grouped GEMMs, weighted atomic accumulation into out
    moe_gemm1<<<dim3(NF / 64, NCAP / 64, NE), 256>>>(x, w_gate, w_up);
    moe_gemm2<<<dim3(NH / 64, NCAP / 64, NE), 256>>>(w_down, out);
}

// round 13
// speedup vs baseline: 1.0014x; 1.0014x over previous
#include <cuda_runtime.h>
#include <math.h>

#define NT   2048      // tokens (2*1024)
#define NH   2048      // hidden
#define NE   64        // experts
#define NK   6         // top_k
#define NF   768       // moe intermediate
#define NG   8         // groups
#define EPG  8         // experts per group
#define NKG  4         // topk groups
#define NCAP 384       // capacity per expert
#define RSCALE 2.5f

// ---------------- scratch (device globals; no allocation allowed) ----------
__device__ float g_logits[NT * NE];
__device__ int   g_cnt[NE];
__device__ int   g_tok[NE * NCAP];
__device__ float g_wgt[NE * NCAP];
__device__ float g_hbuf[(size_t)NE * NCAP * NF];   // 75.5 MB
__device__ float g_sbuf[(size_t)NT * NF];          // 6.3 MB

// ---------------------------------------------------------------------------
__global__ void zero_cnt_kernel() {
    int i = threadIdx.x;
    if (i < NE) g_cnt[i] = 0;
}

// ---------------- router logits: X[NT,NH] @ gate_w[NH,NE] -> g_logits ------
__global__ void router_gemm(const float* __restrict__ X,
                            const float* __restrict__ Wg) {
    __shared__ __align__(16) float As[64][16];
    __shared__ __align__(16) float Bs[16][64];
    int bm = blockIdx.x * 64;
    int tid = threadIdx.x;
    int tx = tid & 15, ty = tid >> 4;
    int arow = tid >> 2, akg = tid & 3;
    int brow = tid >> 4, bng = tid & 15;
    float acc[4][4] = {};
    for (int k0 = 0; k0 < NH; k0 += 16) {
        *(float4*)&As[arow][akg * 4] =
            *(const float4*)&X[(size_t)(bm + arow) * NH + k0 + akg * 4];
        *(float4*)&Bs[brow][bng * 4] =
            *(const float4*)&Wg[(size_t)(k0 + brow) * NE + bng * 4];
        __syncthreads();
#pragma unroll
        for (int kk = 0; kk < 16; kk++) {
            float4 b4 = *(const float4*)&Bs[kk][tx * 4];
            float a[4];
#pragma unroll
            for (int i = 0; i < 4; i++) a[i] = As[ty * 4 + i][kk];
#pragma unroll
            for (int i = 0; i < 4; i++) {
                acc[i][0] += a[i] * b4.x;
                acc[i][1] += a[i] * b4.y;
                acc[i][2] += a[i] * b4.z;
                acc[i][3] += a[i] * b4.w;
            }
        }
        __syncthreads();
    }
#pragma unroll
    for (int i = 0; i < 4; i++)
#pragma unroll
        for (int j = 0; j < 4; j++)
            g_logits[(size_t)(bm + ty * 4 + i) * NE + tx * 4 + j] = acc[i][j];
}

// ---------------- grouped top-k routing + scatter ---------------------------
__global__ void topk_route(const float* __restrict__ bias) {
    int t = blockIdx.x * blockDim.x + threadIdx.x;
    if (t >= NT) return;
    float s[NE], sb[NE];
#pragma unroll 8
    for (int e = 0; e < NE; e++) {
        float l = g_logits[(size_t)t * NE + e];
        float sv = 1.f / (1.f + expf(-l));
        s[e] = sv;
        sb[e] = sv + bias[e];
    }
    // group scores = sum of top-2 biased scores per group
    float gsc[NG];
#pragma unroll
    for (int g = 0; g < NG; g++) {
        float m1 = -INFINITY, m2 = -INFINITY;
#pragma unroll
        for (int j = 0; j < EPG; j++) {
            float v = sb[g * EPG + j];
            if (v > m1) { m2 = m1; m1 = v; }
            else if (v > m2) { m2 = v; }
        }
        gsc[g] = m1 + m2;
    }
    // top-NKG groups (ties -> lowest index, matching jax top_k)
    bool gsel[NG];
#pragma unroll
    for (int g = 0; g < NG; g++) gsel[g] = false;
    for (int r = 0; r < NKG; r++) {
        int bi = 0; float bv = -INFINITY;
        for (int g = 0; g < NG; g++)
            if (!gsel[g] && gsc[g] > bv) { bv = gsc[g]; bi = g; }
        gsel[bi] = true;
    }
    // top-NK experts within selected groups by biased score
    bool used[NE];
#pragma unroll
    for (int e = 0; e < NE; e++) used[e] = false;
    int ids[NK];
    float ws[NK];
    float wsum = 0.f;
    for (int r = 0; r < NK; r++) {
        int bi = 0; float bv = -INFINITY;
        for (int e = 0; e < NE; e++) {
            if (used[e] || !gsel[e / EPG]) continue;
            if (sb[e] > bv) { bv = sb[e]; bi = e; }
        }
        used[bi] = true;
        ids[r] = bi;
        ws[r] = s[bi];   // weights come from UNBIASED scores
        wsum += s[bi];
    }
    float inv = RSCALE / wsum;
    for (int r = 0; r < NK; r++) {
        int e = ids[r];
        int slot = atomicAdd(&g_cnt[e], 1);
        if (slot < NCAP) {
            g_tok[e * NCAP + slot] = t;
            g_wgt[e * NCAP + slot] = ws[r] * inv;
        }
    }
}

// ---------------- grouped SwiGLU GEMM1: hbuf = silu(Xe@Wg) * (Xe@Wu) --------
__global__ void moe_gemm1(const float* __restrict__ X,
                          const float* __restrict__ Wg,
                          const float* __restrict__ Wu) {
    int e = blockIdx.z;
    int cnt = g_cnt[e]; if (cnt > NCAP) cnt = NCAP;
    int row0 = blockIdx.y * 64;
    if (row0 >= cnt) return;
    int n0 = blockIdx.x * 64;

    __shared__ __align__(16) float As[64][16];
    __shared__ __align__(16) float Bg[16][64];
    __shared__ __align__(16) float Bu[16][64];
    __shared__ int toks[64];

    int tid = threadIdx.x;
    if (tid < 64) {
        int r = row0 + tid;
        toks[tid] = (r < cnt) ? g_tok[e * NCAP + r] : 0;
    }
    __syncthreads();

    int tx = tid & 15, ty = tid >> 4;
    int arow = tid >> 2, akg = tid & 3;
    int brow = tid >> 4, bng = tid & 15;
    const float* wg = Wg + (size_t)e * NH * NF;
    const float* wu = Wu + (size_t)e * NH * NF;
    float ag[4][4] = {}, au[4][4] = {};

    for (int k0 = 0; k0 < NH; k0 += 16) {
        *(float4*)&As[arow][akg * 4] =
            *(const float4*)&X[(size_t)toks[arow] * NH + k0 + akg * 4];
        *(float4*)&Bg[brow][bng * 4] =
            *(const float4*)&wg[(size_t)(k0 + brow) * NF + n0 + bng * 4];
        *(float4*)&Bu[brow][bng * 4] =
            *(const float4*)&wu[(size_t)(k0 + brow) * NF + n0 + bng * 4];
        __syncthreads();
#pragma unroll
        for (int kk = 0; kk < 16; kk++) {
            float4 bg4 = *(const float4*)&Bg[kk][tx * 4];
            float4 bu4 = *(const float4*)&Bu[kk][tx * 4];
            float a[4];
#pragma unroll
            for (int i = 0; i < 4; i++) a[i] = As[ty * 4 + i][kk];
#pragma unroll
            for (int i = 0; i < 4; i++) {
                ag[i][0] += a[i] * bg4.x; ag[i][1] += a[i] * bg4.y;
                ag[i][2] += a[i] * bg4.z; ag[i][3] += a[i] * bg4.w;
                au[i][0] += a[i] * bu4.x; au[i][1] += a[i] * bu4.y;
                au[i][2] += a[i] * bu4.z; au[i][3] += a[i] * bu4.w;
            }
        }
        __syncthreads();
    }

    float* hb = g_hbuf + (size_t)e * NCAP * NF;
#pragma unroll
    for (int i = 0; i < 4; i++) {
        int r = row0 + ty * 4 + i;
        if (r >= cnt) continue;
#pragma unroll
        for (int j = 0; j < 4; j++) {
            float g = ag[i][j];
            float h = (g / (1.f + expf(-g))) * au[i][j];
            hb[(size_t)r * NF + n0 + tx * 4 + j] = h;
        }
    }
}

// ---------------- grouped down GEMM: out += w * (hbuf @ Wd) -----------------
__global__ void moe_gemm2(const float* __restrict__ Wd,
                          float* __restrict__ out) {
    int e = blockIdx.z;
    int cnt = g_cnt[e]; if (cnt > NCAP) cnt = NCAP;
    int row0 = blockIdx.y * 64;
    if (row0 >= cnt) return;
    int n0 = blockIdx.x * 64;

    __shared__ __align__(16) float As[64][16];
    __shared__ __align__(16) float Bs[16][64];

    const float* hb = g_hbuf + (size_t)e * NCAP * NF;
    const float* wd = Wd + (size_t)e * NF * NH;

    int tid = threadIdx.x;
    int tx = tid & 15, ty = tid >> 4;
    int arow = tid >> 2, akg = tid & 3;
    int brow = tid >> 4, bng = tid & 15;
    float acc[4][4] = {};

    for (int k0 = 0; k0 < NF; k0 += 16) {
        *(float4*)&As[arow][akg * 4] =
            *(const float4*)&hb[(size_t)(row0 + arow) * NF + k0 + akg * 4];
        *(float4*)&Bs[brow][bng * 4] =
            *(const float4*)&wd[(size_t)(k0 + brow) * NH + n0 + bng * 4];
        __syncthreads();
#pragma unroll
        for (int kk = 0; kk < 16; kk++) {
            float4 b4 = *(const float4*)&Bs[kk][tx * 4];
            float a[4];
#pragma unroll
            for (int i = 0; i < 4; i++) a[i] = As[ty * 4 + i][kk];
#pragma unroll
            for (int i = 0; i < 4; i++) {
                acc[i][0] += a[i] * b4.x; acc[i][1] += a[i] * b4.y;
                acc[i][2] += a[i] * b4.z; acc[i][3] += a[i] * b4.w;
            }
        }
        __syncthreads();
    }

#pragma unroll
    for (int i = 0; i < 4; i++) {
        int r = row0 + ty * 4 + i;
        if (r >= cnt) continue;
        int tok = g_tok[e * NCAP + r];
        float w = g_wgt[e * NCAP + r];
        float* op = out + (size_t)tok * NH + n0 + tx * 4;
#pragma unroll
        for (int j = 0; j < 4; j++)
            atomicAdd(op + j, acc[i][j] * w);
    }
}

// ---------------- shared expert GEMM1: sbuf = silu(X@Wg)*(X@Wu) -------------
__global__ void shared_gemm1(const float* __restrict__ X,
                             const float* __restrict__ Wg,
                             const float* __restrict__ Wu) {
    int row0 = blockIdx.y * 64;
    int n0 = blockIdx.x * 64;

    __shared__ __align__(16) float As[64][16];
    __shared__ __align__(16) float Bg[16][64];
    __shared__ __align__(16) float Bu[16][64];

    int tid = threadIdx.x;
    int tx = tid & 15, ty = tid >> 4;
    int arow = tid >> 2, akg = tid & 3;
    int brow = tid >> 4, bng = tid & 15;
    float ag[4][4] = {}, au[4][4] = {};

    for (int k0 = 0; k0 < NH; k0 += 16) {
        *(float4*)&As[arow][akg * 4] =
            *(const float4*)&X[(size_t)(row0 + arow) * NH + k0 + akg * 4];
        *(float4*)&Bg[brow][bng * 4] =
            *(const float4*)&Wg[(size_t)(k0 + brow) * NF + n0 + bng * 4];
        *(float4*)&Bu[brow][bng * 4] =
            *(const float4*)&Wu[(size_t)(k0 + brow) * NF + n0 + bng * 4];
        __syncthreads();
#pragma unroll
        for (int kk = 0; kk < 16; kk++) {
            float4 bg4 = *(const float4*)&Bg[kk][tx * 4];
            float4 bu4 = *(const float4*)&Bu[kk][tx * 4];
            float a[4];
#pragma unroll
            for (int i = 0; i < 4; i++) a[i] = As[ty * 4 + i][kk];
#pragma unroll
            for (int i = 0; i < 4; i++) {
                ag[i][0] += a[i] * bg4.x; ag[i][1] += a[i] * bg4.y;
                ag[i][2] += a[i] * bg4.z; ag[i][3] += a[i] * bg4.w;
                au[i][0] += a[i] * bu4.x; au[i][1] += a[i] * bu4.y;
                au[i][2] += a[i] * bu4.z; au[i][3] += a[i] * bu4.w;
            }
        }
        __syncthreads();
    }

#pragma unroll
    for (int i = 0; i < 4; i++) {
        int r = row0 + ty * 4 + i;
#pragma unroll
        for (int j = 0; j < 4; j++) {
            float g = ag[i][j];
            float h = (g / (1.f + expf(-g))) * au[i][j];
            g_sbuf[(size_t)r * NF + n0 + tx * 4 + j] = h;
        }
    }
}

// ---------------- shared expert GEMM2: out = sbuf @ Wd (plain store) --------
__global__ void shared_gemm2(const float* __restrict__ Wd,
                             float* __restrict__ out) {
    int row0 = blockIdx.y * 64;
    int n0 = blockIdx.x * 64;

    __shared__ __align__(16) float As[64][16];
    __shared__ __align__(16) float Bs[16][64];

    int tid = threadIdx.x;
    int tx = tid & 15, ty = tid >> 4;
    int arow = tid >> 2, akg = tid & 3;
    int brow = tid >> 4, bng = tid & 15;
    float acc[4][4] = {};

    for (int k0 = 0; k0 < NF; k0 += 16) {
        *(float4*)&As[arow][akg * 4] =
            *(const float4*)&g_sbuf[(size_t)(row0 + arow) * NF + k0 + akg * 4];
        *(float4*)&Bs[brow][bng * 4] =
            *(const float4*)&Wd[(size_t)(k0 + brow) * NH + n0 + bng * 4];
        __syncthreads();
#pragma unroll
        for (int kk = 0; kk < 16; kk++) {
            float4 b4 = *(const float4*)&Bs[kk][tx * 4];
            float a[4];
#pragma unroll
            for (int i = 0; i < 4; i++) a[i] = As[ty * 4 + i][kk];
#pragma unroll
            for (int i = 0; i < 4; i++) {
                acc[i][0] += a[i] * b4.x; acc[i][1] += a[i] * b4.y;
                acc[i][2] += a[i] * b4.z; acc[i][3] += a[i] * b4.w;
            }
        }
        __syncthreads();
    }

#pragma unroll
    for (int i = 0; i < 4; i++) {
        int r = row0 + ty * 4 + i;
#pragma unroll
        for (int j = 0; j < 4; j++)
            out[(size_t)r * NH + n0 + tx * 4 + j] = acc[i][j];
    }
}

// ---------------------------------------------------------------------------
extern "C" void kernel_launch(void* const* d_in, const int* in_sizes, int n_in,
                              void* d_out, int out_size) {
    const float* x       = (const float*)d_in[0];
    const float* gate_w  = (const float*)d_in[1];
    const float* bias    = (const float*)d_in[2];
    const float* w_gate  = (const float*)d_in[3];
    const float* w_up    = (const float*)d_in[4];
    const float* w_down  = (const float*)d_in[5];
    const float* ws_gate = (const float*)d_in[6];
    const float* ws_up   = (const float*)d_in[7];
    const float* ws_down = (const float*)d_in[8];
    float* out = (float*)d_out;

    zero_cnt_kernel<<<1, 64>>>();
    router_gemm<<<NT / 64, 256>>>(x, gate_w);
    topk_route<<<NT / 256, 256>>>(bias);

    // shared expert first: plain stores initialize the (poisoned) output
    shared_gemm1<<<dim3(NF / 64, NT / 64), 256>>>(x, ws_gate, ws_up);
    shared_gemm2<<<dim3(NH / 64, NT / 64), 256>>>(ws_down, out);

    // routed experts: grouped GEMMs, weighted atomic accumulation into out
    moe_gemm1<<<dim3(NF / 64, NCAP / 64, NE), 256>>>(x, w_gate, w_up);
    moe_gemm2<<<dim3(NH / 64, NCAP / 64, NE), 256>>>(w_down, out);
}